// round 12
// baseline (speedup 1.0000x reference)
#include <cuda_runtime.h>
#include <math.h>
#include <stdint.h>

// FootAndBall ball-detection post-process — ONE kernel (detect + fused tail).
//  in : [16, 2, 540, 960] fp32 logits
//  out: [16, 100, 5] fp32 (x1,y1,x2,y2,score), score desc (idx asc on ties).
//
//  Phase 1 (all 720 blocks): d = x1-x0 (NMS on d == NMS on softmax prob,
//    monotone). Software-pipelined float4 streaming NMS (groups of 4 rows,
//    double buffered). Candidates -> block smem queue + smem histogram;
//    block-local top-100 cut filters to ~110/block before ONE contiguous
//    per-batch flush. Global top-100 ⊆ union of block-local top-100s; queue
//    overflow falls back to direct unfiltered append (superset -> correct).
//  Phase 2 (last-arriving block per batch, 16 of 720): register-resident
//    select over the ~5k filtered candidates (one unpredicated LDG.64 burst,
//    RPT=20/thread), smem histogram + log-parallel cut, collect from
//    registers, exact (p desc, idx asc) rank, box write, state reset.
//    Survivor arrays overlay the dead block queue -> smem unchanged (33KB).
//  Rationale: every separately-launched 16-block kernel in this session cost
//  a fixed 25-37us regardless of its work (low-grid launch/throttle floor);
//  the tail inside this 720-block kernel avoids that entirely.
//  __device__ globals start zero-initialized; the tail restores zeros.

#define BB   16
#define HH   540
#define WW   960
#define HWSZ (HH * WW)
#define KK   100

#define NT    256                 // threads per block (8 warps)
#define RPB   12                  // rows per block; 540 = 45 * 12
#define NBY   45                  // blocks per batch
#define QC    2048                // block smem queue entries (16 KB)
#define HB    4096                // histogram bins (top 12 flipped bits)
#define CAP   2048                // tail survivor capacity (expected ~200)
#define CAPG  65536               // per-batch global candidate capacity
#define RPT   20                  // tail: candidates per thread (256*20=5120)

__device__ int    g_cnt [BB];
__device__ int    g_done[BB];
__device__ float2 g_cand[BB][CAPG];

// ---------------------------------------------------------------------------
// Exact softmax channel-1 prob from d = fl(x1-x0). Matches jax.nn.softmax:
// one exp arg is exactly 0 and fl(x0-x1) == -d exactly. (rel_err ~1e-12.)
// ---------------------------------------------------------------------------
__device__ __forceinline__ float prob_from_d(float d) {
#ifdef __FAST_MATH__
    double dd = (double)d;
    double p = (d >= 0.0f) ? (1.0 / (exp(-dd) + 1.0))
                           : (exp(dd) / (exp(dd) + 1.0));
    return (float)p;
#else
    if (d >= 0.0f) { float e0 = expf(-d); return 1.0f / (e0 + 1.0f); }
    else           { float e1 = expf(d);  return e1 / (1.0f + e1);  }
#endif
}

// Order-preserving bit flip: float compare == unsigned compare after flip.
__device__ __forceinline__ unsigned fflip(float f) {
    unsigned u = __float_as_uint(f);
    return u ^ (((unsigned)((int)u >> 31)) | 0x80000000u);
}

// ---------------------------------------------------------------------------
// Log-parallel cut over a 4096-bin smem histogram, 256 threads.
// *s_cut = flipped-bits threshold with count(>= thr) >= KK (0 if total < KK).
// Caller zeroes *s_cut + syncs before; must sync after.
// ---------------------------------------------------------------------------
__device__ __forceinline__ void cut_scan256(const int* __restrict__ hist,
                                            int* __restrict__ s_wtot,
                                            unsigned* __restrict__ s_cut,
                                            int t) {
    const int lane = t & 31;
    const int w    = t >> 5;
    const int seg  = 255 - t;                // descending bin order
    int val = 0;
    const int4* h4 = (const int4*)(hist + seg * 16);
    #pragma unroll
    for (int j = 0; j < 4; j++) { int4 a = h4[j]; val += a.x + a.y + a.z + a.w; }

    int incl = val;
    #pragma unroll
    for (int sh = 1; sh < 32; sh <<= 1) {
        int n = __shfl_up_sync(0xffffffffu, incl, sh);
        if (lane >= sh) incl += n;
    }
    if (lane == 31) s_wtot[w] = incl;
    __syncthreads();
    if (t < 8) {
        int v = s_wtot[t];
        int inc = v;
        #pragma unroll
        for (int sh = 1; sh < 8; sh <<= 1) {
            int n = __shfl_up_sync(0x000000ffu, inc, sh);
            if (t >= sh) inc += n;
        }
        s_wtot[t] = inc - v;
    }
    __syncthreads();
    int excl = incl - val + s_wtot[w];       // count strictly above seg
    if (excl < KK && excl + val >= KK) {     // unique boundary thread
        int above = excl;
        int cut = seg * 16;
        #pragma unroll
        for (int c = seg * 16 + 15; c >= seg * 16; c--) {
            int hv = hist[c];
            if (above + hv >= KK) { cut = c; break; }
            above += hv;
        }
        *s_cut = ((unsigned)cut) << 20;
    }
}

// ---------------------------------------------------------------------------
// Fused kernel. Grid (1, 45, 16), block 256 (8 warps x 120 output cols).
// ---------------------------------------------------------------------------
__global__ __launch_bounds__(NT) void fused_kernel(const float* __restrict__ in,
                                                   float* __restrict__ out) {
    __shared__ __align__(16) int shist[HB];  // 16 KB
    __shared__ __align__(16) float2 s_q[QC]; // 16 KB; tail overlays s_d/s_i
    __shared__ int    s_wtot[8];
    __shared__ unsigned s_bcut;
    __shared__ int    s_qcnt, s_keep, s_gbase, s_sel;

    const int b    = blockIdx.z;
    const int by   = blockIdx.y;
    const int tid  = threadIdx.x;
    const int w    = tid >> 5;
    const int lane = tid & 31;

    const int  c0     = w * 120 - 4 + 4 * lane;          // lane's first column
    const bool colok  = ((unsigned)c0 < (unsigned)WW);
    const int  cc     = colok ? c0 : 0;                  // clamped load column
    const bool laneok = (lane >= 1) && (lane <= 30);
    const int  r0     = by * RPB;

    #pragma unroll
    for (int i = tid; i < HB; i += NT) shist[i] = 0;
    if (tid == 0) { s_qcnt = 0; s_keep = 0; s_bcut = 0u; }
    __syncthreads();

    const float* __restrict__ p0 = in + (size_t)b * 2 * HWSZ;
    const float* __restrict__ p1 = p0 + HWSZ;
    int*    __restrict__ gctr = &g_cnt[b];
    float2* __restrict__ gcd  = g_cand[b];

    #define LDROW(R, A, Bv) {                                                  \
        int _rr = (R) < 0 ? 0 : ((R) >= HH ? HH - 1 : (R));                    \
        size_t _o = (size_t)_rr * WW + cc;                                     \
        A  = __ldg(reinterpret_cast<const float4*>(p0 + _o));                  \
        Bv = __ldg(reinterpret_cast<const float4*>(p1 + _o)); }

    #define CVT(A, Bv, R, D) {                                                 \
        if (colok && ((unsigned)(R) < (unsigned)HH))                            \
            D = make_float4(Bv.x - A.x, Bv.y - A.y, Bv.z - A.z, Bv.w - A.w);    \
        else                                                                    \
            D = make_float4(-INFINITY, -INFINITY, -INFINITY, -INFINITY); }

    #define H3MAX4(D, HM) {                                                    \
        float _dl = __shfl_up_sync(0xffffffffu, (D).w, 1);                      \
        float _dr = __shfl_down_sync(0xffffffffu, (D).x, 1);                    \
        (HM).x = fmaxf(_dl,   fmaxf((D).x, (D).y));                             \
        (HM).y = fmaxf((D).x, fmaxf((D).y, (D).z));                             \
        (HM).z = fmaxf((D).y, fmaxf((D).z, (D).w));                             \
        (HM).w = fmaxf((D).z, fmaxf((D).w, _dr)); }

    #define EMIT1(K, V, IDX)                                                   \
        if (K) {                                                               \
            atomicAdd(&shist[fflip(V) >> 20], 1);                              \
            int _p = atomicAdd(&s_qcnt, 1);                                    \
            float2 _v = make_float2(V, __int_as_float(IDX));                   \
            if (_p < QC) s_q[_p] = _v;                                         \
            else { int _g = atomicAdd(gctr, 1);                                \
                   if (_g < CAPG) gcd[_g] = _v; }                              \
        }

    #define EMITROW(DC, HA, HBv, HC, R) {                                      \
        float _m0 = fmaxf((HA).x, fmaxf((HBv).x, (HC).x));                     \
        float _m1 = fmaxf((HA).y, fmaxf((HBv).y, (HC).y));                     \
        float _m2 = fmaxf((HA).z, fmaxf((HBv).z, (HC).z));                     \
        float _m3 = fmaxf((HA).w, fmaxf((HBv).w, (HC).w));                     \
        bool _k0 = laneok && ((DC).x >= _m0);                                  \
        bool _k1 = laneok && ((DC).y >= _m1);                                  \
        bool _k2 = laneok && ((DC).z >= _m2);                                  \
        bool _k3 = laneok && ((DC).w >= _m3);                                  \
        if (_k0 | _k1 | _k2 | _k3) {                                           \
            int _ib = (R) * WW + c0;                                           \
            EMIT1(_k0, (DC).x, _ib)                                            \
            EMIT1(_k1, (DC).y, _ib + 1)                                        \
            EMIT1(_k2, (DC).z, _ib + 2)                                        \
            EMIT1(_k3, (DC).w, _ib + 3)                                        \
        } }

    #define LOAD_GROUP(P, BASE)                                                \
        LDROW((BASE) + 1, P##1a, P##1b)                                        \
        LDROW((BASE) + 2, P##2a, P##2b)                                        \
        LDROW((BASE) + 3, P##3a, P##3b)                                        \
        LDROW((BASE) + 4, P##4a, P##4b)

    #define COMPUTE_GROUP(P, BASE) {                                           \
        float4 _d1, _d2, _d3, _d4, _h1, _h2, _h3, _h4;                         \
        CVT(P##1a, P##1b, (BASE) + 1, _d1)  H3MAX4(_d1, _h1)                   \
        CVT(P##2a, P##2b, (BASE) + 2, _d2)  H3MAX4(_d2, _h2)                   \
        CVT(P##3a, P##3b, (BASE) + 3, _d3)  H3MAX4(_d3, _h3)                   \
        CVT(P##4a, P##4b, (BASE) + 4, _d4)  H3MAX4(_d4, _h4)                   \
        EMITROW(dB, hmA, hmB, _h1, (BASE))                                     \
        EMITROW(_d1, hmB, _h1, _h2, (BASE) + 1)                                \
        EMITROW(_d2, _h1, _h2, _h3, (BASE) + 2)                                \
        EMITROW(_d3, _h2, _h3, _h4, (BASE) + 3)                                \
        hmA = _h3; hmB = _h4; dB = _d4; }

    {
        float4 A1a, A1b, A2a, A2b, A3a, A3b, A4a, A4b;
        float4 B1a, B1b, B2a, B2b, B3a, B3b, B4a, B4b;
        float4 hmA, hmB, dB;
        {
            float4 xa, xb, dm;
            LDROW(r0 - 1, xa, xb)
            LOAD_GROUP(A, r0)                    // rows r0+1..r0+4 (early)
            float4 ya, yb;
            LDROW(r0, ya, yb)
            LOAD_GROUP(B, r0 + 4)                // rows r0+5..r0+8 (early)
            CVT(xa, xb, r0 - 1, dm)  H3MAX4(dm, hmA)
            CVT(ya, yb, r0, dB)      H3MAX4(dB, hmB)
        }
        COMPUTE_GROUP(A, r0)                     // rows r0..r0+3
        LOAD_GROUP(A, r0 + 8)                    // rows r0+9..r0+12 (early)
        COMPUTE_GROUP(B, r0 + 4)                 // rows r0+4..r0+7
        COMPUTE_GROUP(A, r0 + 8)                 // rows r0+8..r0+11
    }

    // --- Block-local top-100 cut + filtered contiguous flush ---------------
    __syncthreads();
    cut_scan256(shist, s_wtot, &s_bcut, tid);
    __syncthreads();
    const unsigned bcut = s_bcut;
    const int qn = min(s_qcnt, QC);

    int cnt = 0;
    for (int i = tid; i < qn; i += NT)
        cnt += (fflip(s_q[i].x) >= bcut);
    if (cnt) atomicAdd(&s_keep, cnt);
    __syncthreads();
    if (tid == 0) {
        s_gbase = (s_keep > 0) ? atomicAdd(gctr, s_keep) : 0;
        s_keep = 0;
    }
    __syncthreads();
    for (int i = tid; i < qn; i += NT) {
        float2 v = s_q[i];
        if (fflip(v.x) >= bcut) {
            int p = s_gbase + atomicAdd(&s_keep, 1);
            if (p < CAPG) gcd[p] = v;
        }
    }

    // =====================================================================
    // Tail: last-arriving block of this batch becomes the selector.
    // =====================================================================
    __threadfence();                 // release candidate writes
    __syncthreads();
    if (tid == 0)
        s_sel = (atomicAdd(&g_done[b], 1) == NBY - 1) ? 1 : 0;
    __syncthreads();
    if (!s_sel) return;
    __threadfence();                 // acquire side

    const int n = min(*((volatile int*)gctr), CAPG);
    if (tid == 0) { g_cnt[b] = 0; g_done[b] = 0; }   // reset for next replay

    // Re-init smem for the tail; survivor arrays overlay the dead queue.
    #pragma unroll
    for (int i = tid; i < HB; i += NT) shist[i] = 0;
    if (tid == 0) { s_bcut = 0u; s_keep = 0; }
    float* s_d = (float*)s_q;              // 2048 floats (8 KB)
    int*   s_i = ((int*)s_q) + CAP;        // next 2048 ints (8 KB)

    // ---- One unpredicated load burst: all RPT loads issue back-to-back ----
    float2 v[RPT];
    #pragma unroll
    for (int j = 0; j < RPT; j++) {
        int idx = tid + j * NT;
        int ii  = (idx < n) ? idx : 0;     // clamp keeps the load legal
        v[j] = __ldg(gcd + ii);
    }
    __syncthreads();                        // hist zero + overlay safe

    // ---- Histogram from registers ----
    #pragma unroll
    for (int j = 0; j < RPT; j++)
        if (tid + j * NT < n)
            atomicAdd(&shist[fflip(v[j].x) >> 20], 1);
    for (int i = NT * RPT + tid; i < n; i += NT)      // rare overflow
        atomicAdd(&shist[fflip(gcd[i].x) >> 20], 1);
    __syncthreads();

    cut_scan256(shist, s_wtot, &s_bcut, tid);
    __syncthreads();
    const unsigned cutbits = s_bcut;

    // ---- Collect survivors from registers ----
    #pragma unroll
    for (int j = 0; j < RPT; j++) {
        if (tid + j * NT < n && fflip(v[j].x) >= cutbits) {
            int pos = atomicAdd(&s_keep, 1);
            if (pos < CAP) { s_d[pos] = v[j].x; s_i[pos] = __float_as_int(v[j].y); }
        }
    }
    for (int i = NT * RPT + tid; i < n; i += NT) {    // rare overflow
        float2 vv = gcd[i];
        if (fflip(vv.x) >= cutbits) {
            int pos = atomicAdd(&s_keep, 1);
            if (pos < CAP) { s_d[pos] = vv.x; s_i[pos] = __float_as_int(vv.y); }
        }
    }
    __syncthreads();

    const int C = min(s_keep, CAP);

    // ---- Exact p in place, then exact stable rank: p desc, idx asc ----
    for (int e = tid; e < C; e += NT) s_d[e] = prob_from_d(s_d[e]);
    __syncthreads();

    for (int e = tid; e < C; e += NT) {
        const float p  = s_d[e];
        const int   id = s_i[e];
        int rank = 0;
        for (int j = 0; j < C; j++) {
            float pj = s_d[j];
            rank += (pj > p) || (pj == p && s_i[j] < id);
        }
        if (rank < KK) {
            int ww = id % WW;
            int hh = id / WW;
            float xc = (float)ww * 4.0f + 1.5f;
            float yc = (float)hh * 4.0f + 1.5f;
            float* o = out + ((size_t)b * KK + rank) * 5;
            o[0] = xc - 10.0f;
            o[1] = yc - 10.0f;
            o[2] = xc + 10.0f;
            o[3] = yc + 10.0f;
            o[4] = p;
        }
    }
}

// ---------------------------------------------------------------------------
extern "C" void kernel_launch(void* const* d_in, const int* in_sizes, int n_in,
                              void* d_out, int out_size) {
    const float* in = (const float*)d_in[0];
    float* out = (float*)d_out;

    dim3 grid(1, NBY, BB);                    // (1, 45, 16) = 720 blocks
    fused_kernel<<<grid, NT>>>(in, out);
}